// round 1
// baseline (speedup 1.0000x reference)
#include <cuda_runtime.h>
#include <cstdint>

// Problem constants (fixed by the dataset)
#define FF  512   // input features
#define HD  64    // H1*D1
#define NH  8     // heads layer 1
#define NC  10    // classes / layer-2 width
#define NMAX 50000

// -------- scratch (static device globals; no allocation allowed) ----------
static __device__ float g_h1  [NMAX*HD];   // layer-1 projected features
static __device__ float g_as1 [NMAX*NH];   // alpha_src layer 1
static __device__ float g_ad1 [NMAX*NH];   // alpha_dst layer 1
static __device__ float g_den1[NMAX*NH];   // softmax denominators layer 1
static __device__ float g_acc1[NMAX*HD];   // weighted message accumulator L1
static __device__ float g_x2  [NMAX*HD];   // elu(layer-1 output) = layer-2 input
static __device__ float g_h2  [NMAX*NC];   // layer-2 projected features
static __device__ float g_as2 [NMAX];
static __device__ float g_ad2 [NMAX];
static __device__ float g_den2[NMAX];
static __device__ float g_acc2[NMAX*NC];
static __device__ int   g_is32;            // 1 if edge_index is really int32

// -------- edge dtype sniffer ----------------------------------------------
// If edge_index is int32 but we read it as int64, each read combines two
// int32 indices -> value has a (almost surely) nonzero high half >= N.
__global__ void k_detect(const long long* __restrict__ e, long long E, long long N) {
    if (blockIdx.x == 0 && threadIdx.x == 0) {
        int is32 = 0;
        long long cnt = E < 256 ? E : 256;
        for (long long i = 0; i < cnt; i++) {
            long long v = e[i];
            if (v < 0 || v >= N) { is32 = 1; break; }
        }
        g_is32 = is32;
    }
}

// -------- zero accumulators -----------------------------------------------
__global__ void k_zero(int N) {
    int stride = gridDim.x * blockDim.x;
    int total  = N * HD;
    for (int i = blockIdx.x * blockDim.x + threadIdx.x; i < total; i += stride) {
        g_acc1[i] = 0.f;
        if (i < N * NH) g_den1[i] = 0.f;
        if (i < N * NC) g_acc2[i] = 0.f;
        if (i < N)      g_den2[i] = 0.f;
    }
}

// -------- GEMM1: h1 = x @ W1  [N,512]x[512,64] ----------------------------
// 64x64 output tile per block, 256 threads, 4x4 register micro-tile.
__global__ void k_gemm1(const float* __restrict__ x, const float* __restrict__ W, int N) {
    __shared__ float As[32][68];   // [k][m], padded for alignment/banks
    __shared__ float Bs[32][64];   // [k][n]
    int tid = threadIdx.x;
    int m0  = blockIdx.x * 64;
    int ty  = tid >> 4, tx = tid & 15;
    float acc[4][4] = {};

    for (int kk = 0; kk < FF; kk += 32) {
        // Load A tile: 64 rows x 32 k  (2 float4 per thread), store transposed
        #pragma unroll
        for (int j = 0; j < 2; j++) {
            int t4  = tid + 256 * j;
            int row = t4 >> 3, c4 = t4 & 7;
            float4 v = make_float4(0.f, 0.f, 0.f, 0.f);
            if (m0 + row < N)
                v = *(const float4*)&x[(long long)(m0 + row) * FF + kk + c4 * 4];
            As[c4*4+0][row] = v.x; As[c4*4+1][row] = v.y;
            As[c4*4+2][row] = v.z; As[c4*4+3][row] = v.w;
        }
        // Load B tile: 32 k x 64 n
        #pragma unroll
        for (int j = 0; j < 2; j++) {
            int t4 = tid + 256 * j;
            int kr = t4 >> 4, n4 = t4 & 15;
            *(float4*)&Bs[kr][n4*4] = *(const float4*)&W[(kk + kr) * 64 + n4 * 4];
        }
        __syncthreads();
        #pragma unroll
        for (int k = 0; k < 32; k++) {
            float4 a = *(const float4*)&As[k][ty * 4];
            float4 b = *(const float4*)&Bs[k][tx * 4];
            float av[4] = {a.x, a.y, a.z, a.w};
            float bv[4] = {b.x, b.y, b.z, b.w};
            #pragma unroll
            for (int i = 0; i < 4; i++)
                #pragma unroll
                for (int j = 0; j < 4; j++)
                    acc[i][j] += av[i] * bv[j];
        }
        __syncthreads();
    }
    #pragma unroll
    for (int i = 0; i < 4; i++) {
        int row = m0 + ty * 4 + i;
        if (row < N) {
            #pragma unroll
            for (int j = 0; j < 4; j++)
                g_h1[row * 64 + tx * 4 + j] = acc[i][j];
        }
    }
}

// -------- alpha projections layer 1 ---------------------------------------
__global__ void k_alpha1(const float* __restrict__ a_src, const float* __restrict__ a_dst, int N) {
    int idx = blockIdx.x * blockDim.x + threadIdx.x;
    if (idx >= N * NH) return;
    int n = idx >> 3, h = idx & 7;
    const float* hp = &g_h1[n * 64 + h * 8];
    float s = 0.f, d = 0.f;
    #pragma unroll
    for (int i = 0; i < 8; i++) {
        float v = hp[i];
        s += v * a_src[h * 8 + i];
        d += v * a_dst[h * 8 + i];
    }
    g_as1[idx] = s;
    g_ad1[idx] = d;
}

// -------- edge pass layer 1 (one warp per edge) ---------------------------
// Softmax max-subtraction is skipped (logits are O(1), exp cannot overflow;
// softmax is shift-invariant). Accumulate sum(w*h[src]) and sum(w) per dst.
__global__ void k_edge1(const void* __restrict__ ei, long long E, int N) {
    long long wid = ((long long)blockIdx.x * blockDim.x + threadIdx.x) >> 5;
    int lane = threadIdx.x & 31;
    long long EN = E + (long long)N;
    if (wid >= EN) return;

    long long s, d;
    if (wid >= E) { s = d = wid - E; }                                  // self-loop
    else if (g_is32) { const int* p = (const int*)ei;        s = p[wid]; d = p[E + wid]; }
    else             { const long long* p = (const long long*)ei; s = p[wid]; d = p[E + wid]; }

    float wl = 0.f;
    if (lane < NH) {
        float e = g_as1[s * NH + lane] + g_ad1[d * NH + lane];
        e = e > 0.f ? e : 0.2f * e;            // LeakyReLU(0.2)
        wl = expf(e);
        atomicAdd(&g_den1[d * NH + lane], wl);
    }
    float wa = __shfl_sync(0xffffffffu, wl, lane >> 3);        // head of feature lane
    float wb = __shfl_sync(0xffffffffu, wl, (lane >> 3) + 4);  // head of feature lane+32
    float va = g_h1[s * 64 + lane];
    float vb = g_h1[s * 64 + 32 + lane];
    atomicAdd(&g_acc1[d * 64 + lane],      wa * va);
    atomicAdd(&g_acc1[d * 64 + 32 + lane], wb * vb);
}

// -------- finalize layer 1: normalize + bias + ELU ------------------------
__global__ void k_fin1(const float* __restrict__ b1, int N) {
    int idx = blockIdx.x * blockDim.x + threadIdx.x;
    if (idx >= N * 64) return;
    int n = idx >> 6, f = idx & 63;
    float v = g_acc1[idx] / g_den1[n * NH + (f >> 3)] + b1[f];
    g_x2[idx] = v > 0.f ? v : expm1f(v);       // ELU(alpha=1)
}

// -------- GEMM2 + alpha projections layer 2 (warp per node) ---------------
__global__ void k_gemm2(const float* __restrict__ W2,
                        const float* __restrict__ a_src2,
                        const float* __restrict__ a_dst2, int N) {
    long long gt = (long long)blockIdx.x * blockDim.x + threadIdx.x;
    long long wid = gt >> 5;
    int lane = threadIdx.x & 31;
    if (wid >= N) return;
    float v0 = g_x2[wid * 64 + lane];
    float v1 = g_x2[wid * 64 + 32 + lane];
    float asum = 0.f, adsum = 0.f;
    #pragma unroll
    for (int c = 0; c < NC; c++) {
        float s = v0 * W2[lane * NC + c] + v1 * W2[(lane + 32) * NC + c];
        #pragma unroll
        for (int o = 16; o; o >>= 1) s += __shfl_down_sync(0xffffffffu, s, o);
        if (lane == 0) {
            g_h2[wid * NC + c] = s;
            asum  += s * a_src2[c];
            adsum += s * a_dst2[c];
        }
    }
    if (lane == 0) { g_as2[wid] = asum; g_ad2[wid] = adsum; }
}

// -------- edge pass layer 2 (one thread per edge) -------------------------
__global__ void k_edge2(const void* __restrict__ ei, long long E, int N) {
    long long i = (long long)blockIdx.x * blockDim.x + threadIdx.x;
    long long EN = E + (long long)N;
    if (i >= EN) return;
    long long s, d;
    if (i >= E) { s = d = i - E; }
    else if (g_is32) { const int* p = (const int*)ei;        s = p[i]; d = p[E + i]; }
    else             { const long long* p = (const long long*)ei; s = p[i]; d = p[E + i]; }
    float e = g_as2[s] + g_ad2[d];
    e = e > 0.f ? e : 0.2f * e;
    float w = expf(e);
    atomicAdd(&g_den2[d], w);
    const float* hp = &g_h2[s * NC];
    #pragma unroll
    for (int c = 0; c < NC; c++)
        atomicAdd(&g_acc2[d * NC + c], w * hp[c]);
}

// -------- finalize layer 2: normalize + bias + log_softmax ----------------
__global__ void k_fin2(const float* __restrict__ b2, float* __restrict__ out, int N) {
    int n = blockIdx.x * blockDim.x + threadIdx.x;
    if (n >= N) return;
    float inv = 1.f / g_den2[n];
    float v[NC];
    float m = -1e30f;
    #pragma unroll
    for (int c = 0; c < NC; c++) {
        v[c] = g_acc2[n * NC + c] * inv + b2[c];
        m = fmaxf(m, v[c]);
    }
    float ssum = 0.f;
    #pragma unroll
    for (int c = 0; c < NC; c++) ssum += expf(v[c] - m);
    float l = logf(ssum);
    #pragma unroll
    for (int c = 0; c < NC; c++) out[n * NC + c] = v[c] - m - l;
}

// ---------------------------------------------------------------------------
extern "C" void kernel_launch(void* const* d_in, const int* in_sizes, int n_in,
                              void* d_out, int out_size) {
    const float* x   = (const float*)d_in[0];
    const void*  ei  = d_in[1];
    const float* W1  = (const float*)d_in[2];
    const float* as1 = (const float*)d_in[3];
    const float* ad1 = (const float*)d_in[4];
    const float* b1  = (const float*)d_in[5];
    const float* W2  = (const float*)d_in[6];
    const float* as2 = (const float*)d_in[7];
    const float* ad2 = (const float*)d_in[8];
    const float* b2  = (const float*)d_in[9];

    int       N = in_sizes[0] / FF;           // 50000
    long long E = (long long)in_sizes[1] / 2; // 1.6M (element count / 2 rows)
    long long EN = E + (long long)N;
    float* out = (float*)d_out;

    k_detect<<<1, 32>>>((const long long*)ei, E, N);
    k_zero<<<512, 256>>>(N);
    k_gemm1<<<(N + 63) / 64, 256>>>(x, W1, N);
    k_alpha1<<<(N * NH + 255) / 256, 256>>>(as1, ad1, N);
    {
        long long threads = EN * 32;          // warp per edge
        unsigned blocks = (unsigned)((threads + 255) / 256);
        k_edge1<<<blocks, 256>>>(ei, E, N);
    }
    k_fin1<<<(N * 64 + 255) / 256, 256>>>(b1, N);
    {
        long long threads = (long long)N * 32; // warp per node
        k_gemm2<<<(unsigned)((threads + 255) / 256), 256>>>(W2, as2, ad2, N);
    }
    k_edge2<<<(unsigned)((EN + 255) / 256), 256>>>(ei, E, N);
    k_fin2<<<(N + 255) / 256, 256>>>(b2, out, N);
}

// round 2
// speedup vs baseline: 1.3704x; 1.3704x over previous
#include <cuda_runtime.h>
#include <cstdint>

// Problem constants (fixed by the dataset)
#define FF  512   // input features
#define HD  64    // H1*D1
#define NH  8     // heads layer 1
#define NC  10    // classes / layer-2 width
#define NMAX 50000
#define EMAX 1700000   // E (1.6M) + N self-loops, rounded up

// -------- scratch (static device globals; no allocation allowed) ----------
static __device__ float g_h1  [NMAX*HD];   // layer-1 projected features
static __device__ float g_as1 [NMAX*NH];   // alpha_src layer 1
static __device__ float g_ad1 [NMAX*NH];   // alpha_dst layer 1
static __device__ float g_x2  [NMAX*HD];   // elu(layer-1 output) = layer-2 input
static __device__ float g_h2  [NMAX*NC];   // layer-2 projected features
static __device__ float g_as2 [NMAX];
static __device__ float g_ad2 [NMAX];
static __device__ int   g_cnt [NMAX];      // per-dst degree
static __device__ int   g_off [NMAX+1];    // CSR offsets
static __device__ int   g_cur [NMAX];      // scatter cursors
static __device__ int   g_csr [EMAX];      // CSR src indices (dst-bucketed)
static __device__ int   g_is32;            // 1 if edge_index is really int32

// -------- edge dtype sniffer ----------------------------------------------
__global__ void k_detect(const long long* __restrict__ e, long long E, long long N) {
    if (blockIdx.x == 0 && threadIdx.x == 0) {
        int is32 = 0;
        long long cnt = E < 256 ? E : 256;
        for (long long i = 0; i < cnt; i++) {
            long long v = e[i];
            if (v < 0 || v >= N) { is32 = 1; break; }
        }
        g_is32 = is32;
    }
}

// -------- zero degree counters --------------------------------------------
__global__ void k_zero(int N) {
    int i = blockIdx.x * blockDim.x + threadIdx.x;
    if (i < N) g_cnt[i] = 0;
}

// -------- CSR build: histogram --------------------------------------------
__global__ void k_hist(const void* __restrict__ ei, long long E, int N) {
    long long i = (long long)blockIdx.x * blockDim.x + threadIdx.x;
    long long EN = E + (long long)N;
    if (i >= EN) return;
    int d;
    if (i >= E) d = (int)(i - E);
    else if (g_is32) d = ((const int*)ei)[E + i];
    else             d = (int)((const long long*)ei)[E + i];
    atomicAdd(&g_cnt[d], 1);
}

// -------- CSR build: exclusive scan (single block, 1024 threads) ----------
__global__ void k_scan(int N) {
    __shared__ int part[1024];
    int t = threadIdx.x;
    int chunk = (N + 1023) >> 10;
    int beg = t * chunk;
    int end = beg + chunk; if (end > N) end = N;
    int sum = 0;
    for (int i = beg; i < end; i++) sum += g_cnt[i];
    part[t] = sum;
    __syncthreads();
    for (int o = 1; o < 1024; o <<= 1) {
        int v = (t >= o) ? part[t - o] : 0;
        __syncthreads();
        if (t >= o) part[t] += v;
        __syncthreads();
    }
    int run = t ? part[t - 1] : 0;
    for (int i = beg; i < end; i++) {
        g_off[i] = run;
        g_cur[i] = run;
        run += g_cnt[i];
    }
    if (t == 1023) g_off[N] = part[1023];
}

// -------- CSR build: scatter ----------------------------------------------
__global__ void k_scatter(const void* __restrict__ ei, long long E, int N) {
    long long i = (long long)blockIdx.x * blockDim.x + threadIdx.x;
    long long EN = E + (long long)N;
    if (i >= EN) return;
    int s, d;
    if (i >= E) { s = d = (int)(i - E); }
    else if (g_is32) { const int* p = (const int*)ei; s = p[i]; d = p[E + i]; }
    else { const long long* p = (const long long*)ei; s = (int)p[i]; d = (int)p[E + i]; }
    int pos = atomicAdd(&g_cur[d], 1);
    g_csr[pos] = s;
}

// -------- GEMM1: h1 = x @ W1  [N,512]x[512,64], alpha1 fused in epilogue --
__global__ void k_gemm1(const float* __restrict__ x, const float* __restrict__ W,
                        const float* __restrict__ a_src, const float* __restrict__ a_dst,
                        int N) {
    __shared__ float As[32][68];   // [k][m], padded
    __shared__ float Bs[32][64];   // [k][n]
    __shared__ float sAsrc[64], sAdst[64];
    int tid = threadIdx.x;
    if (tid < 64) { sAsrc[tid] = a_src[tid]; sAdst[tid] = a_dst[tid]; }
    int m0  = blockIdx.x * 64;
    int ty  = tid >> 4, tx = tid & 15;
    float acc[4][4] = {};

    for (int kk = 0; kk < FF; kk += 32) {
        #pragma unroll
        for (int j = 0; j < 2; j++) {
            int t4  = tid + 256 * j;
            int row = t4 >> 3, c4 = t4 & 7;
            float4 v = make_float4(0.f, 0.f, 0.f, 0.f);
            if (m0 + row < N)
                v = *(const float4*)&x[(long long)(m0 + row) * FF + kk + c4 * 4];
            As[c4*4+0][row] = v.x; As[c4*4+1][row] = v.y;
            As[c4*4+2][row] = v.z; As[c4*4+3][row] = v.w;
        }
        #pragma unroll
        for (int j = 0; j < 2; j++) {
            int t4 = tid + 256 * j;
            int kr = t4 >> 4, n4 = t4 & 15;
            *(float4*)&Bs[kr][n4*4] = *(const float4*)&W[(kk + kr) * 64 + n4 * 4];
        }
        __syncthreads();
        #pragma unroll
        for (int k = 0; k < 32; k++) {
            float4 a = *(const float4*)&As[k][ty * 4];
            float4 b = *(const float4*)&Bs[k][tx * 4];
            float av[4] = {a.x, a.y, a.z, a.w};
            float bv[4] = {b.x, b.y, b.z, b.w};
            #pragma unroll
            for (int i = 0; i < 4; i++)
                #pragma unroll
                for (int j = 0; j < 4; j++)
                    acc[i][j] += av[i] * bv[j];
        }
        __syncthreads();
    }
    // Epilogue: store h1 + fused alpha_src/alpha_dst projections.
    // Thread covers features tx*4..tx*4+3 -> head h = tx>>1; pair (tx^1) holds
    // the other half of the head. Shuffles are unconditional (full warp).
    int h = tx >> 1, base = h * 8 + (tx & 1) * 4;
    #pragma unroll
    for (int i = 0; i < 4; i++) {
        int row = m0 + ty * 4 + i;
        float s = 0.f, dd = 0.f;
        #pragma unroll
        for (int j = 0; j < 4; j++) {
            s  += acc[i][j] * sAsrc[base + j];
            dd += acc[i][j] * sAdst[base + j];
        }
        float s2 = __shfl_xor_sync(0xffffffffu, s, 1);
        float d2 = __shfl_xor_sync(0xffffffffu, dd, 1);
        if (row < N) {
            #pragma unroll
            for (int j = 0; j < 4; j++)
                g_h1[row * 64 + tx * 4 + j] = acc[i][j];
            if (!(tx & 1)) {
                g_as1[row * 8 + h] = s + s2;
                g_ad1[row * 8 + h] = dd + d2;
            }
        }
    }
}

// -------- aggregation layer 1 (warp per dst, CSR, no atomics) -------------
// Fuses softmax-weighted aggregation + normalize + bias + ELU.
// Max-subtraction skipped: logits are O(1) (softmax is shift-invariant).
__global__ void k_agg1(const float* __restrict__ b1, int N) {
    int d = (blockIdx.x * blockDim.x + threadIdx.x) >> 5;
    int lane = threadIdx.x & 31;
    if (d >= N) return;
    int beg = g_off[d], end = g_off[d + 1];
    float ad_l = (lane < NH) ? g_ad1[d * NH + lane] : 0.f;
    float acc0 = 0.f, acc1 = 0.f, den = 0.f;
    for (int i = beg; i < end; i++) {
        int s = g_csr[i];
        float w = 0.f;
        if (lane < NH) {
            float e = g_as1[s * NH + lane] + ad_l;
            e = e > 0.f ? e : 0.2f * e;          // LeakyReLU(0.2)
            w = __expf(e);
            den += w;
        }
        float wa = __shfl_sync(0xffffffffu, w, lane >> 3);
        float wb = __shfl_sync(0xffffffffu, w, (lane >> 3) + 4);
        acc0 += wa * g_h1[s * 64 + lane];
        acc1 += wb * g_h1[s * 64 + 32 + lane];
    }
    float dena = __shfl_sync(0xffffffffu, den, lane >> 3);
    float denb = __shfl_sync(0xffffffffu, den, (lane >> 3) + 4);
    float v0 = acc0 / dena + b1[lane];
    float v1 = acc1 / denb + b1[32 + lane];
    g_x2[d * 64 + lane]      = v0 > 0.f ? v0 : expm1f(v0);  // ELU
    g_x2[d * 64 + 32 + lane] = v1 > 0.f ? v1 : expm1f(v1);
}

// -------- GEMM2 + alpha projections layer 2 (warp per node) ---------------
__global__ void k_gemm2(const float* __restrict__ W2,
                        const float* __restrict__ a_src2,
                        const float* __restrict__ a_dst2, int N) {
    int wid = (blockIdx.x * blockDim.x + threadIdx.x) >> 5;
    int lane = threadIdx.x & 31;
    if (wid >= N) return;
    float v0 = g_x2[wid * 64 + lane];
    float v1 = g_x2[wid * 64 + 32 + lane];
    float asum = 0.f, adsum = 0.f;
    #pragma unroll
    for (int c = 0; c < NC; c++) {
        float s = v0 * W2[lane * NC + c] + v1 * W2[(lane + 32) * NC + c];
        #pragma unroll
        for (int o = 16; o; o >>= 1) s += __shfl_down_sync(0xffffffffu, s, o);
        if (lane == 0) {
            g_h2[wid * NC + c] = s;
            asum  += s * a_src2[c];
            adsum += s * a_dst2[c];
        }
    }
    if (lane == 0) { g_as2[wid] = asum; g_ad2[wid] = adsum; }
}

// -------- aggregation layer 2 (warp per dst, lanes over edges) ------------
// Fuses aggregation + normalize + bias + log_softmax; writes final output.
__global__ void k_agg2(const float* __restrict__ b2, float* __restrict__ out, int N) {
    int d = (blockIdx.x * blockDim.x + threadIdx.x) >> 5;
    int lane = threadIdx.x & 31;
    if (d >= N) return;
    int beg = g_off[d], end = g_off[d + 1];
    float ad_d = g_ad2[d];
    float acc[NC] = {};
    float den = 0.f;
    for (int i = beg + lane; i < end; i += 32) {
        int s = g_csr[i];
        float e = g_as2[s] + ad_d;
        e = e > 0.f ? e : 0.2f * e;
        float w = __expf(e);
        den += w;
        const float* hp = &g_h2[s * NC];
        #pragma unroll
        for (int c = 0; c < NC; c++) acc[c] += w * hp[c];
    }
    #pragma unroll
    for (int o = 16; o; o >>= 1) {
        den += __shfl_down_sync(0xffffffffu, den, o);
        #pragma unroll
        for (int c = 0; c < NC; c++)
            acc[c] += __shfl_down_sync(0xffffffffu, acc[c], o);
    }
    if (lane == 0) {
        float inv = 1.f / den;
        float v[NC], m = -1e30f;
        #pragma unroll
        for (int c = 0; c < NC; c++) {
            v[c] = acc[c] * inv + b2[c];
            m = fmaxf(m, v[c]);
        }
        float ssum = 0.f;
        #pragma unroll
        for (int c = 0; c < NC; c++) ssum += __expf(v[c] - m);
        float l = __logf(ssum);
        #pragma unroll
        for (int c = 0; c < NC; c++) out[d * NC + c] = v[c] - m - l;
    }
}

// ---------------------------------------------------------------------------
extern "C" void kernel_launch(void* const* d_in, const int* in_sizes, int n_in,
                              void* d_out, int out_size) {
    const float* x   = (const float*)d_in[0];
    const void*  ei  = d_in[1];
    const float* W1  = (const float*)d_in[2];
    const float* as1 = (const float*)d_in[3];
    const float* ad1 = (const float*)d_in[4];
    const float* b1  = (const float*)d_in[5];
    const float* W2  = (const float*)d_in[6];
    const float* as2 = (const float*)d_in[7];
    const float* ad2 = (const float*)d_in[8];
    const float* b2  = (const float*)d_in[9];

    int       N  = in_sizes[0] / FF;           // 50000
    long long E  = (long long)in_sizes[1] / 2; // 1.6M
    long long EN = E + (long long)N;
    float* out = (float*)d_out;

    k_detect<<<1, 32>>>((const long long*)ei, E, N);
    k_zero<<<(N + 255) / 256, 256>>>(N);
    k_hist<<<(unsigned)((EN + 255) / 256), 256>>>(ei, E, N);
    k_scan<<<1, 1024>>>(N);
    k_scatter<<<(unsigned)((EN + 255) / 256), 256>>>(ei, E, N);
    k_gemm1<<<(N + 63) / 64, 256>>>(x, W1, as1, ad1, N);
    k_agg1<<<(unsigned)(((long long)N * 32 + 255) / 256), 256>>>(b1, N);
    k_gemm2<<<(unsigned)(((long long)N * 32 + 255) / 256), 256>>>(W2, as2, ad2, N);
    k_agg2<<<(unsigned)(((long long)N * 32 + 255) / 256), 256>>>(b2, out, N);
}

// round 3
// speedup vs baseline: 1.7000x; 1.2405x over previous
#include <cuda_runtime.h>
#include <cstdint>

// Problem constants (fixed by the dataset)
#define FF  512   // input features
#define HD  64    // H1*D1
#define NH  8     // heads layer 1
#define NC  10    // classes / layer-2 width
#define NMAX 50000
#define EMAX 1700000   // E (1.6M) + N self-loops, rounded up
#define SCANB 256      // scan tile
#define NBMAX ((NMAX + SCANB - 1) / SCANB)   // 196 scan blocks

// -------- scratch (static device globals; no allocation allowed) ----------
static __device__ float g_h1  [NMAX*HD];   // layer-1 projected features
static __device__ float g_as1 [NMAX*NH];   // alpha_src layer 1
static __device__ float g_ad1 [NMAX*NH];   // alpha_dst layer 1
static __device__ float g_x2  [NMAX*HD];   // elu(layer-1 output) = layer-2 input
static __device__ float g_h2  [NMAX*NC];   // layer-2 projected features
static __device__ float g_as2 [NMAX];
static __device__ float g_ad2 [NMAX];
static __device__ int   g_cnt [NMAX];      // per-dst degree
static __device__ int   g_off [NMAX+1];    // CSR offsets
static __device__ int   g_cur [NMAX];      // scatter cursors
static __device__ int   g_csr [EMAX];      // CSR src indices (dst-bucketed)
static __device__ int   g_bsum[NBMAX];     // scan block totals -> offsets
static __device__ int   g_is32;            // 1 if edge_index is really int32

// -------- edge dtype sniffer ----------------------------------------------
__global__ void k_detect(const long long* __restrict__ e, long long E, long long N) {
    if (blockIdx.x == 0 && threadIdx.x == 0) {
        int is32 = 0;
        long long cnt = E < 256 ? E : 256;
        for (long long i = 0; i < cnt; i++) {
            long long v = e[i];
            if (v < 0 || v >= N) { is32 = 1; break; }
        }
        g_is32 = is32;
    }
}

// -------- zero degree counters --------------------------------------------
__global__ void k_zero(int N) {
    int i = blockIdx.x * blockDim.x + threadIdx.x;
    if (i < N) g_cnt[i] = 0;
}

// -------- CSR build: histogram --------------------------------------------
__global__ void k_hist(const void* __restrict__ ei, long long E, int N) {
    long long i = (long long)blockIdx.x * blockDim.x + threadIdx.x;
    long long EN = E + (long long)N;
    if (i >= EN) return;
    int d;
    if (i >= E) d = (int)(i - E);
    else if (g_is32) d = ((const int*)ei)[E + i];
    else             d = (int)((const long long*)ei)[E + i];
    atomicAdd(&g_cnt[d], 1);
}

// -------- CSR build: two-level parallel exclusive scan --------------------
// Level 1: block-local exclusive scan; write local prefix + block total.
__global__ void k_scan1(int N) {
    __shared__ int sh[SCANB];
    int t = threadIdx.x;
    int i = blockIdx.x * SCANB + t;
    int v = (i < N) ? g_cnt[i] : 0;
    sh[t] = v;
    __syncthreads();
    #pragma unroll
    for (int o = 1; o < SCANB; o <<= 1) {
        int u = (t >= o) ? sh[t - o] : 0;
        __syncthreads();
        sh[t] += u;
        __syncthreads();
    }
    if (i < N) g_off[i] = sh[t] - v;         // exclusive local prefix
    if (t == SCANB - 1) g_bsum[blockIdx.x] = sh[t];
}

// Level 2: single block scans the block totals (nb <= 256).
__global__ void k_scan2(int nb) {
    __shared__ int sh[SCANB];
    int t = threadIdx.x;
    int v = (t < nb) ? g_bsum[t] : 0;
    sh[t] = v;
    __syncthreads();
    #pragma unroll
    for (int o = 1; o < SCANB; o <<= 1) {
        int u = (t >= o) ? sh[t - o] : 0;
        __syncthreads();
        sh[t] += u;
        __syncthreads();
    }
    if (t < nb) g_bsum[t] = sh[t] - v;       // exclusive block offset
}

// Level 3: add block offsets, init cursors, set sentinel.
__global__ void k_scan3(int N, int total) {
    int i = blockIdx.x * blockDim.x + threadIdx.x;
    if (i < N) {
        int o = g_off[i] + g_bsum[blockIdx.x * (blockDim.x / SCANB) + (threadIdx.x / SCANB) + (blockIdx.x * blockDim.x) / SCANB - blockIdx.x * (blockDim.x / SCANB) - (threadIdx.x / SCANB)]; // placeholder avoided below
    }
    // (simple form: blockDim == SCANB so block index == scan tile index)
    if (i < N) {
        int o = g_off[i] + g_bsum[i / SCANB];
        g_off[i] = o;
        g_cur[i] = o;
    }
    if (i == 0) g_off[N] = total;
}

// -------- CSR build: scatter ----------------------------------------------
__global__ void k_scatter(const void* __restrict__ ei, long long E, int N) {
    long long i = (long long)blockIdx.x * blockDim.x + threadIdx.x;
    long long EN = E + (long long)N;
    if (i >= EN) return;
    int s, d;
    if (i >= E) { s = d = (int)(i - E); }
    else if (g_is32) { const int* p = (const int*)ei; s = p[i]; d = p[E + i]; }
    else { const long long* p = (const long long*)ei; s = (int)p[i]; d = (int)p[E + i]; }
    int pos = atomicAdd(&g_cur[d], 1);
    g_csr[pos] = s;
}

// -------- GEMM1: h1 = x @ W1  [N,512]x[512,64], alpha1 fused in epilogue --
__global__ void k_gemm1(const float* __restrict__ x, const float* __restrict__ W,
                        const float* __restrict__ a_src, const float* __restrict__ a_dst,
                        int N) {
    __shared__ float As[32][68];   // [k][m], padded
    __shared__ float Bs[32][64];   // [k][n]
    __shared__ float sAsrc[64], sAdst[64];
    int tid = threadIdx.x;
    if (tid < 64) { sAsrc[tid] = a_src[tid]; sAdst[tid] = a_dst[tid]; }
    int m0  = blockIdx.x * 64;
    int ty  = tid >> 4, tx = tid & 15;
    float acc[4][4] = {};

    for (int kk = 0; kk < FF; kk += 32) {
        #pragma unroll
        for (int j = 0; j < 2; j++) {
            int t4  = tid + 256 * j;
            int row = t4 >> 3, c4 = t4 & 7;
            float4 v = make_float4(0.f, 0.f, 0.f, 0.f);
            if (m0 + row < N)
                v = *(const float4*)&x[(long long)(m0 + row) * FF + kk + c4 * 4];
            As[c4*4+0][row] = v.x; As[c4*4+1][row] = v.y;
            As[c4*4+2][row] = v.z; As[c4*4+3][row] = v.w;
        }
        #pragma unroll
        for (int j = 0; j < 2; j++) {
            int t4 = tid + 256 * j;
            int kr = t4 >> 4, n4 = t4 & 15;
            *(float4*)&Bs[kr][n4*4] = *(const float4*)&W[(kk + kr) * 64 + n4 * 4];
        }
        __syncthreads();
        #pragma unroll
        for (int k = 0; k < 32; k++) {
            float4 a = *(const float4*)&As[k][ty * 4];
            float4 b = *(const float4*)&Bs[k][tx * 4];
            float av[4] = {a.x, a.y, a.z, a.w};
            float bv[4] = {b.x, b.y, b.z, b.w};
            #pragma unroll
            for (int i = 0; i < 4; i++)
                #pragma unroll
                for (int j = 0; j < 4; j++)
                    acc[i][j] += av[i] * bv[j];
        }
        __syncthreads();
    }
    // Epilogue: store h1 + fused alpha_src/alpha_dst projections.
    int h = tx >> 1, base = h * 8 + (tx & 1) * 4;
    #pragma unroll
    for (int i = 0; i < 4; i++) {
        int row = m0 + ty * 4 + i;
        float s = 0.f, dd = 0.f;
        #pragma unroll
        for (int j = 0; j < 4; j++) {
            s  += acc[i][j] * sAsrc[base + j];
            dd += acc[i][j] * sAdst[base + j];
        }
        float s2 = __shfl_xor_sync(0xffffffffu, s, 1);
        float d2 = __shfl_xor_sync(0xffffffffu, dd, 1);
        if (row < N) {
            #pragma unroll
            for (int j = 0; j < 4; j++)
                g_h1[row * 64 + tx * 4 + j] = acc[i][j];
            if (!(tx & 1)) {
                g_as1[row * 8 + h] = s + s2;
                g_ad1[row * 8 + h] = dd + d2;
            }
        }
    }
}

// -------- aggregation layer 1 (warp per dst, CSR, no atomics) -------------
__global__ void k_agg1(const float* __restrict__ b1, int N) {
    int d = (blockIdx.x * blockDim.x + threadIdx.x) >> 5;
    int lane = threadIdx.x & 31;
    if (d >= N) return;
    int beg = g_off[d], end = g_off[d + 1];
    float ad_l = (lane < NH) ? g_ad1[d * NH + lane] : 0.f;
    float acc0 = 0.f, acc1 = 0.f, den = 0.f;
    for (int i = beg; i < end; i++) {
        int s = g_csr[i];
        float w = 0.f;
        if (lane < NH) {
            float e = g_as1[s * NH + lane] + ad_l;
            e = e > 0.f ? e : 0.2f * e;          // LeakyReLU(0.2)
            w = __expf(e);
            den += w;
        }
        float wa = __shfl_sync(0xffffffffu, w, lane >> 3);
        float wb = __shfl_sync(0xffffffffu, w, (lane >> 3) + 4);
        acc0 += wa * g_h1[s * 64 + lane];
        acc1 += wb * g_h1[s * 64 + 32 + lane];
    }
    float dena = __shfl_sync(0xffffffffu, den, lane >> 3);
    float denb = __shfl_sync(0xffffffffu, den, (lane >> 3) + 4);
    float v0 = acc0 / dena + b1[lane];
    float v1 = acc1 / denb + b1[32 + lane];
    g_x2[d * 64 + lane]      = v0 > 0.f ? v0 : expm1f(v0);  // ELU
    g_x2[d * 64 + 32 + lane] = v1 > 0.f ? v1 : expm1f(v1);
}

// -------- GEMM2 + alpha projections layer 2 (warp per node) ---------------
__global__ void k_gemm2(const float* __restrict__ W2,
                        const float* __restrict__ a_src2,
                        const float* __restrict__ a_dst2, int N) {
    int wid = (blockIdx.x * blockDim.x + threadIdx.x) >> 5;
    int lane = threadIdx.x & 31;
    if (wid >= N) return;
    float v0 = g_x2[wid * 64 + lane];
    float v1 = g_x2[wid * 64 + 32 + lane];
    float asum = 0.f, adsum = 0.f;
    #pragma unroll
    for (int c = 0; c < NC; c++) {
        float s = v0 * W2[lane * NC + c] + v1 * W2[(lane + 32) * NC + c];
        #pragma unroll
        for (int o = 16; o; o >>= 1) s += __shfl_down_sync(0xffffffffu, s, o);
        if (lane == 0) {
            g_h2[wid * NC + c] = s;
            asum  += s * a_src2[c];
            adsum += s * a_dst2[c];
        }
    }
    if (lane == 0) { g_as2[wid] = asum; g_ad2[wid] = adsum; }
}

// -------- aggregation layer 2 (warp per dst, lanes over edges) ------------
__global__ void k_agg2(const float* __restrict__ b2, float* __restrict__ out, int N) {
    int d = (blockIdx.x * blockDim.x + threadIdx.x) >> 5;
    int lane = threadIdx.x & 31;
    if (d >= N) return;
    int beg = g_off[d], end = g_off[d + 1];
    float ad_d = g_ad2[d];
    float acc[NC] = {};
    float den = 0.f;
    for (int i = beg + lane; i < end; i += 32) {
        int s = g_csr[i];
        float e = g_as2[s] + ad_d;
        e = e > 0.f ? e : 0.2f * e;
        float w = __expf(e);
        den += w;
        const float* hp = &g_h2[s * NC];
        #pragma unroll
        for (int c = 0; c < NC; c++) acc[c] += w * hp[c];
    }
    #pragma unroll
    for (int o = 16; o; o >>= 1) {
        den += __shfl_down_sync(0xffffffffu, den, o);
        #pragma unroll
        for (int c = 0; c < NC; c++)
            acc[c] += __shfl_down_sync(0xffffffffu, acc[c], o);
    }
    if (lane == 0) {
        float inv = 1.f / den;
        float v[NC], m = -1e30f;
        #pragma unroll
        for (int c = 0; c < NC; c++) {
            v[c] = acc[c] * inv + b2[c];
            m = fmaxf(m, v[c]);
        }
        float ssum = 0.f;
        #pragma unroll
        for (int c = 0; c < NC; c++) ssum += __expf(v[c] - m);
        float l = __logf(ssum);
        #pragma unroll
        for (int c = 0; c < NC; c++) out[d * NC + c] = v[c] - m - l;
    }
}

// ---------------------------------------------------------------------------
extern "C" void kernel_launch(void* const* d_in, const int* in_sizes, int n_in,
                              void* d_out, int out_size) {
    const float* x   = (const float*)d_in[0];
    const void*  ei  = d_in[1];
    const float* W1  = (const float*)d_in[2];
    const float* as1 = (const float*)d_in[3];
    const float* ad1 = (const float*)d_in[4];
    const float* b1  = (const float*)d_in[5];
    const float* W2  = (const float*)d_in[6];
    const float* as2 = (const float*)d_in[7];
    const float* ad2 = (const float*)d_in[8];
    const float* b2  = (const float*)d_in[9];

    int       N  = in_sizes[0] / FF;           // 50000
    long long E  = (long long)in_sizes[1] / 2; // 1.6M
    long long EN = E + (long long)N;
    int nb = (N + SCANB - 1) / SCANB;          // scan tiles
    float* out = (float*)d_out;

    k_detect<<<1, 32>>>((const long long*)ei, E, N);
    k_zero<<<(N + 255) / 256, 256>>>(N);
    k_hist<<<(unsigned)((EN + 255) / 256), 256>>>(ei, E, N);
    k_scan1<<<nb, SCANB>>>(N);
    k_scan2<<<1, SCANB>>>(nb);
    k_scan3<<<nb, SCANB>>>(N, (int)EN);
    k_scatter<<<(unsigned)((EN + 255) / 256), 256>>>(ei, E, N);
    k_gemm1<<<(N + 63) / 64, 256>>>(x, W1, as1, ad1, N);
    k_agg1<<<(unsigned)(((long long)N * 32 + 255) / 256), 256>>>(b1, N);
    k_gemm2<<<(unsigned)(((long long)N * 32 + 255) / 256), 256>>>(W2, as2, ad2, N);
    k_agg2<<<(unsigned)(((long long)N * 32 + 255) / 256), 256>>>(b2, out, N);
}